// round 17
// baseline (speedup 1.0000x reference)
#include <cuda_runtime.h>
#include <cuda_bf16.h>

#define BB 512
#define SS 1024
#define TT 64

typedef unsigned long long u64;

__device__ __forceinline__ u64 fma2(u64 a, u64 b, u64 c) {
    u64 d;
    asm("fma.rn.f32x2 %0, %1, %2, %3;" : "=l"(d) : "l"(a), "l"(b), "l"(c));
    return d;
}
__device__ __forceinline__ u64 add2(u64 a, u64 b) {
    u64 d;
    asm("add.rn.f32x2 %0, %1, %2;" : "=l"(d) : "l"(a), "l"(b));
    return d;
}
__device__ __forceinline__ u64 pack2(float lo, float hi) {
    u64 d;
    asm("mov.b64 %0, {%1, %2};" : "=l"(d) : "f"(lo), "f"(hi));
    return d;
}
__device__ __forceinline__ void unpack2(u64 v, float& lo, float& hi) {
    asm("mov.b64 {%0, %1}, %2;" : "=f"(lo), "=f"(hi) : "l"(v));
}

#define MM_I32 0
#define MM_F32 1
#define MM_U8  2

__device__ __forceinline__ int mask_at(const void* m, long long idx, int mode) {
    if (mode == MM_I32) return ((const int*)m)[idx] != 0;
    if (mode == MM_F32) return ((const float*)m)[idx] != 0.0f;
    return ((const unsigned char*)m)[idx] != 0;
}

// group-local barrier: 64 threads of group g (IDs 1..4)
#define GBAR() asm volatile("bar.sync %0, 64;" :: "r"(g + 1) : "memory")
// slot barrier: 128 threads (fwd+bwd groups of one slot), IDs 5..6
#define SLBAR() asm volatile("bar.sync %0, 128;" :: "r"(slot + 5) : "memory")

__global__ __launch_bounds__(256, 1)
void crf_loss_kernel(const int* __restrict__ tags,
                     const void* __restrict__ mask,
                     const float* __restrict__ emit,
                     const float* __restrict__ trans,
                     float* __restrict__ out) {
    // [group][seq][buf][col]
    __shared__ __align__(16) float p_s[4][2][2][TT];
    __shared__ float wm_s[4][2];        // normalizer publish per group per seq
    __shared__ float red_s[4][2][2];    // [g][seq][wid]
    __shared__ int   lred[4][2][2];
    __shared__ float tsred[2][2][2];    // [slot][seq][wid]
    __shared__ float comb_w[2][2][TT];  // [slot][seq][col]
    __shared__ float comb_mb[2][2];

    const int tid  = threadIdx.x;
    const int g    = tid >> 6;        // group 0..3; even g -> SMSPs{0,1}, odd -> {2,3}
    const int slot = g >> 1;          // 0..1
    const int bwd  = g & 1;           // 0 = forward, 1 = backward
    const int tp   = tid & 63;
    const int wid  = tp >> 5;
    const int lane = tp & 31;
    const int bid  = blockIdx.x;      // 0..127

    // adjacent-rank pairing: both seqs of a slot have similar length -> full overlap.
    // slot0: ranks {2bid, 2bid+1} (0..255); slot1: {510-2bid, 511-2bid} (256..511).
    const int bA = (slot == 0) ? (2 * bid)     : (510 - 2 * bid);
    const int bB = (slot == 0) ? (2 * bid + 1) : (511 - 2 * bid);

    const int w0 = ((const int*)mask)[0];
    const int mmode = (w0 == 1) ? MM_I32 : ((w0 == 0x3F800000) ? MM_F32 : MM_U8);

    // ---- E operand registers (direction-dependent only; shared by both seqs) ----
    u64 E2[32];
    #pragma unroll
    for (int j = 0; j < 32; j++) {
        float lo, hi;
        if (!bwd) {
            lo = __expf(trans[(2 * j)     * TT + tp]);
            hi = __expf(trans[(2 * j + 1) * TT + tp]);
        } else {
            lo = __expf(trans[tp * TT + 2 * j]);
            hi = __expf(trans[tp * TT + 2 * j + 1]);
        }
        E2[j] = pack2(lo, hi);
    }

    const int strd = bwd ? -TT : TT;

    // ---- per-seq setup: length, split, emit base ----
    #define SETUP_SEQ(X, SEQI, bX)                                                   \
        const float* emitb##X = emit + (size_t)(bX) * SS * TT;                       \
        const int*   tagsb##X = tags + (bX) * SS;                                    \
        int cnt##X = 0;                                                              \
        for (int s = tp; s < SS; s += 64)                                            \
            cnt##X += mask_at(mask, (long long)(bX) * SS + s, mmode);                \
        _Pragma("unroll")                                                            \
        for (int o = 16; o; o >>= 1)                                                 \
            cnt##X += __shfl_xor_sync(0xFFFFFFFFu, cnt##X, o);                       \
        if (lane == 0) lred[g][SEQI][wid] = cnt##X;

    SETUP_SEQ(A, 0, bA)
    SETUP_SEQ(B, 1, bB)
    #undef SETUP_SEQ
    GBAR();
    const int lenA = lred[g][0][0] + lred[g][0][1];
    const int lenB = lred[g][1][0] + lred[g][1][1];
    const int mA = (lenA - 1) >> 1, mB = (lenB - 1) >> 1;
    const int MA = bwd ? (lenA - 1 - mA) : mA;
    const int MB = bwd ? (lenB - 1 - mB) : mB;
    const float* ePA = emitbA + (size_t)(bwd ? (lenA - 1) : 0) * TT + tp;
    const float* ePB = emitbB + (size_t)(bwd ? (lenB - 1) : 0) * TT + tp;

    // ---- total_score (fwd group) for both seqs ----
    if (!bwd) {
        #define TS_SEQ(X, SEQI)                                                      \
        {                                                                            \
            float ts = 0.0f;                                                         \
            for (int s = tp; s < len##X; s += 64) {                                  \
                int tg = tagsb##X[s];                                                \
                ts += emitb##X[(size_t)s * TT + tg];                                 \
                if (s > 0) ts += trans[tagsb##X[s - 1] * TT + tg];                   \
            }                                                                        \
            _Pragma("unroll")                                                        \
            for (int o = 16; o; o >>= 1) ts += __shfl_xor_sync(0xFFFFFFFFu, ts, o);  \
            if (lane == 0) tsred[slot][SEQI][wid] = ts;                              \
        }
        TS_SEQ(A, 0)
        TS_SEQ(B, 1)
        #undef TS_SEQ
    }

    // ---- init both seqs: v0 = exp(e0 - m0), m0 exact group max ----
    float mbA, mbB, m_useA, m_useB, p_valA, p_valB;
    {
        float d0A = ePA[0];
        float d0B = ePB[0];
        float wmA = d0A, wmB = d0B;
        #pragma unroll
        for (int o = 16; o; o >>= 1) {
            wmA = fmaxf(wmA, __shfl_xor_sync(0xFFFFFFFFu, wmA, o));
            wmB = fmaxf(wmB, __shfl_xor_sync(0xFFFFFFFFu, wmB, o));
        }
        if (lane == 0) { red_s[g][0][wid] = wmA; red_s[g][1][wid] = wmB; }
        GBAR();
        m_useA = fmaxf(red_s[g][0][0], red_s[g][0][1]);
        m_useB = fmaxf(red_s[g][1][0], red_s[g][1][1]);
        mbA = m_useA; mbB = m_useB;
        p_valA = __expf(d0A - m_useA);
        p_valB = __expf(d0B - m_useB);
        p_s[g][0][0][tp] = p_valA;
        p_s[g][1][0][tp] = p_valB;
        GBAR();
    }

    // ---- distance-4 emit prefetch rings ----
    float e_bufA[4], e_bufB[4];
    #pragma unroll
    for (int i = 0; i < 4; i++) {
        e_bufA[i] = (1 + i <= MA) ? ePA[(long long)(1 + i) * strd] : 0.0f;
        e_bufB[i] = (1 + i <= MB) ? ePB[(long long)(1 + i) * strd] : 0.0f;
    }

    int bufA = 0, bufB = 0;
    bool pendA = false, pendB = false;

    // ---- dual step: advance BOTH seqs one step, ONE barrier ----
    #define DSTEP(S, KK, PUB_)                                                       \
    {                                                                                \
        if (pendA) { m_useA = wm_s[g][0]; pendA = false; }                           \
        if (pendB) { m_useB = wm_s[g][1]; pendB = false; }                           \
        float eA = e_bufA[(KK)], eB = e_bufB[(KK)];                                  \
        e_bufA[(KK)] = ((S) + 4 <= MA) ? ePA[(long long)((S) + 4) * strd] : 0.0f;    \
        e_bufB[(KK)] = ((S) + 4 <= MB) ? ePB[(long long)((S) + 4) * strd] : 0.0f;    \
        float scA = __expf(mbA + eA - m_useA);                                       \
        float scB = __expf(mbB + eB - m_useB);                                       \
        const ulonglong2* ppA = (const ulonglong2*)p_s[g][0][bufA];                  \
        const ulonglong2* ppB = (const ulonglong2*)p_s[g][1][bufB];                  \
        u64 aA0=0ull, aA1=0ull, aA2=0ull, aA3=0ull;                                  \
        u64 aB0=0ull, aB1=0ull, aB2=0ull, aB3=0ull;                                  \
        _Pragma("unroll")                                                            \
        for (int j = 0; j < 32; j += 4) {                                            \
            ulonglong2 vA0 = ppA[(j >> 1)];                                          \
            ulonglong2 vB0 = ppB[(j >> 1)];                                          \
            ulonglong2 vA1 = ppA[(j >> 1) + 1];                                      \
            ulonglong2 vB1 = ppB[(j >> 1) + 1];                                      \
            aA0 = fma2(vA0.x, E2[j],     aA0);                                       \
            aB0 = fma2(vB0.x, E2[j],     aB0);                                       \
            aA1 = fma2(vA0.y, E2[j + 1], aA1);                                       \
            aB1 = fma2(vB0.y, E2[j + 1], aB1);                                       \
            aA2 = fma2(vA1.x, E2[j + 2], aA2);                                       \
            aB2 = fma2(vB1.x, E2[j + 2], aB2);                                       \
            aA3 = fma2(vA1.y, E2[j + 3], aA3);                                       \
            aB3 = fma2(vB1.y, E2[j + 3], aB3);                                       \
        }                                                                            \
        u64 tA = add2(add2(aA0, aA1), add2(aA2, aA3));                               \
        u64 tB = add2(add2(aB0, aB1), add2(aB2, aB3));                               \
        float lA, hA, lB, hB;                                                        \
        unpack2(tA, lA, hA);                                                         \
        unpack2(tB, lB, hB);                                                         \
        float accA = lA + hA;                                                        \
        float accB = lB + hB;                                                        \
        p_valA = accA * scA;                                                         \
        p_valB = accB * scB;                                                         \
        p_s[g][0][bufA ^ 1][tp] = p_valA;                                            \
        p_s[g][1][bufB ^ 1][tp] = p_valB;                                            \
        if (PUB_) {                                                                  \
            if (tp == 0) {                                                           \
                wm_s[g][0] = mbA + __logf(accA) + eA;                                \
                wm_s[g][1] = mbB + __logf(accB) + eB;                                \
            }                                                                        \
            pendA = true; pendB = true;                                              \
        }                                                                            \
        GBAR();                                                                      \
        mbA = m_useA; mbB = m_useB;                                                  \
        bufA ^= 1; bufB ^= 1;                                                        \
    }

    // ---- single-seq step (tail when one seq is longer) ----
    #define STEP1(X, SEQI, S, KK, PUB_)                                              \
    {                                                                                \
        if (pend##X) { m_use##X = wm_s[g][SEQI]; pend##X = false; }                  \
        float e = e_buf##X[(KK)];                                                    \
        e_buf##X[(KK)] = ((S) + 4 <= M##X) ? eP##X[(long long)((S) + 4) * strd] : 0.0f;\
        float sc = __expf(mb##X + e - m_use##X);                                     \
        const ulonglong2* pp = (const ulonglong2*)p_s[g][SEQI][buf##X];              \
        u64 a0=0ull, a1=0ull, a2=0ull, a3=0ull, a4=0ull, a5=0ull, a6=0ull, a7=0ull;  \
        _Pragma("unroll")                                                            \
        for (int j = 0; j < 32; j += 8) {                                            \
            ulonglong2 v0 = pp[(j >> 1)];                                            \
            ulonglong2 v1 = pp[(j >> 1) + 1];                                        \
            ulonglong2 v2 = pp[(j >> 1) + 2];                                        \
            ulonglong2 v3 = pp[(j >> 1) + 3];                                        \
            a0 = fma2(v0.x, E2[j],     a0);                                          \
            a1 = fma2(v0.y, E2[j + 1], a1);                                          \
            a2 = fma2(v1.x, E2[j + 2], a2);                                          \
            a3 = fma2(v1.y, E2[j + 3], a3);                                          \
            a4 = fma2(v2.x, E2[j + 4], a4);                                          \
            a5 = fma2(v2.y, E2[j + 5], a5);                                          \
            a6 = fma2(v3.x, E2[j + 6], a6);                                          \
            a7 = fma2(v3.y, E2[j + 7], a7);                                          \
        }                                                                            \
        u64 tt = add2(add2(add2(a0, a1), add2(a2, a3)),                              \
                      add2(add2(a4, a5), add2(a6, a7)));                             \
        float flo, fhi;                                                              \
        unpack2(tt, flo, fhi);                                                       \
        float acc = flo + fhi;                                                       \
        p_val##X = acc * sc;                                                         \
        p_s[g][SEQI][buf##X ^ 1][tp] = p_val##X;                                     \
        if (PUB_) {                                                                  \
            if (tp == 0) wm_s[g][SEQI] = mb##X + __logf(acc) + e;                    \
            pend##X = true;                                                          \
        }                                                                            \
        GBAR();                                                                      \
        mb##X = m_use##X;                                                            \
        buf##X ^= 1;                                                                 \
    }

    const int cmn = (MA < MB) ? MA : MB;
    int s = 1;
    for (; s + 3 <= cmn; s += 4) {
        DSTEP(s + 0, 0, false)
        DSTEP(s + 1, 1, false)
        DSTEP(s + 2, 2, false)
        DSTEP(s + 3, 3, true)
    }
    for (; s <= cmn; s++) {
        DSTEP(s, (s - 1) & 3, ((s & 3) == 0))
    }
    // tails (at most one executes)
    for (; s <= MA; s++) {
        STEP1(A, 0, s, (s - 1) & 3, ((s & 3) == 0))
    }
    for (; s <= MB; s++) {
        STEP1(B, 1, s, (s - 1) & 3, ((s & 3) == 0))
    }
    #undef DSTEP
    #undef STEP1

    // ---- combine halves per seq: log Z = mbf + mbw + log sum_t pf*pw*exp(-e_m) ----
    if (bwd) {
        comb_w[slot][0][tp] = p_valA;
        comb_w[slot][1][tp] = p_valB;
        if (tp == 0) { comb_mb[slot][0] = mbA; comb_mb[slot][1] = mbB; }
    }
    SLBAR();
    if (!bwd) {
        float emA = emitbA[(size_t)mA * TT + tp];
        float emB = emitbB[(size_t)mB * TT + tp];
        float prodA = p_valA * comb_w[slot][0][tp] * __expf(-emA);
        float prodB = p_valB * comb_w[slot][1][tp] * __expf(-emB);
        #pragma unroll
        for (int o = 16; o; o >>= 1) {
            prodA += __shfl_xor_sync(0xFFFFFFFFu, prodA, o);
            prodB += __shfl_xor_sync(0xFFFFFFFFu, prodB, o);
        }
        if (lane == 0) { red_s[g][0][wid] = prodA; red_s[g][1][wid] = prodB; }
        GBAR();
        if (tp == 0) {
            float logzA = mbA + comb_mb[slot][0] + __logf(red_s[g][0][0] + red_s[g][0][1]);
            float logzB = mbB + comb_mb[slot][1] + __logf(red_s[g][1][0] + red_s[g][1][1]);
            out[bA] = logzA - (tsred[slot][0][0] + tsred[slot][0][1]);
            out[bB] = logzB - (tsred[slot][1][0] + tsred[slot][1][1]);
        }
    }
}

extern "C" void kernel_launch(void* const* d_in, const int* in_sizes, int n_in,
                              void* d_out, int out_size) {
    const int*   tags  = (const int*)d_in[0];
    const void*  mask  = d_in[1];
    const float* emit  = (const float*)d_in[2];
    const float* trans = (const float*)d_in[3];
    float* out = (float*)d_out;
    (void)in_sizes; (void)n_in; (void)out_size;

    crf_loss_kernel<<<BB / 4, 256>>>(tags, mask, emit, trans, out);
}